// round 10
// baseline (speedup 1.0000x reference)
#include <cuda_runtime.h>
#include <math.h>

#define VOCAB   128000
#define NVEC    (VOCAB / 4)
#define TOPK    50
#define TOPP    0.9f
#define NEGV    (-1000000000.0f)
#define NBINS   4096
#define NCHUNK  (NBINS / 32)
#define CAP     2048
#define ROWSMAX 256
#define SEGS    25
#define VPSEG   (NVEC / SEGS)     // 1280 float4 per segment = 10 * 128
#define K1NT    128
#define BATCH   10
#define K2NT    256
#define LCAP    192               // per-tile candidate staging
#define THRVAL  3.0f              // fixed candidate threshold (fallback covers misses)
#define POISON  (1u << 20)        // forces k2 exact fallback when a tile clips

__device__ unsigned int g_cnt[ROWSMAX];
__device__ unsigned long long g_buf[ROWSMAX * CAP];

__device__ __forceinline__ unsigned int fkey(float f) {
    unsigned int u = __float_as_uint(f);
    return (u & 0x80000000u) ? ~u : (u | 0x80000000u);
}
__device__ __forceinline__ float unkey(unsigned int k) {
    return __uint_as_float((k & 0x80000000u) ? (k & 0x7FFFFFFFu) : ~k);
}

// ---------------- K1: stream read + NEG-fill + tiny candidate collect ----------------
__global__ __launch_bounds__(K1NT)
void k1_stream(const float* __restrict__ logits, float* __restrict__ out) {
    __shared__ unsigned long long lbuf[LCAP];
    __shared__ unsigned int s_c;
    __shared__ unsigned int s_base;

    const int row = blockIdx.y;
    const int seg = blockIdx.x;
    const float4* rp4 = (const float4*)(logits + (size_t)row * VOCAB);
    float4* op4 = (float4*)(out + (size_t)row * VOCAB);
    const int tid = threadIdx.x;
    if (tid == 0) s_c = 0u;
    __syncthreads();

    const float4 neg4 = make_float4(NEGV, NEGV, NEGV, NEGV);
    const int i0 = seg * VPSEG + tid;

    // ---- 10-wide batch: all streaming loads first, then all streaming stores ----
    float4 v[BATCH];
    #pragma unroll
    for (int j = 0; j < BATCH; j++) v[j] = __ldcs(&rp4[i0 + j * K1NT]);
    #pragma unroll
    for (int j = 0; j < BATCH; j++) __stwt(&op4[i0 + j * K1NT], neg4);

    #pragma unroll
    for (int j = 0; j < BATCH; j++) {
        float mx = fmaxf(fmaxf(v[j].x, v[j].y), fmaxf(v[j].z, v[j].w));
        if (mx >= THRVAL) {                       // rare (<0.5% of vectors)
            unsigned int g = (unsigned int)((i0 + j * K1NT) * 4);
            float vals[4] = {v[j].x, v[j].y, v[j].z, v[j].w};
            #pragma unroll
            for (int c = 0; c < 4; c++) {
                if (vals[c] >= THRVAL) {
                    unsigned p = atomicAdd(&s_c, 1u);
                    if (p < LCAP)
                        lbuf[p] = ((unsigned long long)fkey(vals[c]) << 32)
                                | (unsigned long long)(0xFFFFFFFFu - (g + (unsigned)c));
                }
            }
        }
    }
    __syncthreads();

    const unsigned int cnt = s_c;
    if (cnt == 0u) return;
    const unsigned int stored = cnt < LCAP ? cnt : LCAP;
    if (tid == 0) {
        unsigned int add = (cnt > LCAP) ? (cnt + POISON) : cnt;  // clip -> force fallback
        s_base = atomicAdd(&g_cnt[row], add);
    }
    __syncthreads();
    const unsigned int b0 = s_base;
    unsigned long long* gb = &g_buf[(size_t)row * CAP];
    for (unsigned int i = tid; i < stored; i += K1NT) {
        unsigned int p = b0 + i;
        if (p < CAP) gb[p] = lbuf[i];
    }
}

// ---------------- K2: per-row finalize ----------------
__global__ __launch_bounds__(K2NT)
void k2_finalize(const float* __restrict__ logits, float* __restrict__ out) {
    __shared__ union {
        unsigned long long u64[CAP];
        unsigned int       u32[NBINS];
    } sh;
    __shared__ unsigned int chunkSum[NCHUNK];
    __shared__ unsigned int s_cnt;
    __shared__ unsigned int s_thr;
    __shared__ unsigned int s_cntAbove;
    __shared__ int s_needRefine;
    __shared__ int s_m;

    const int row = blockIdx.x;
    const float4* rp4 = (const float4*)(logits + (size_t)row * VOCAB);
    const int tid = threadIdx.x;

    const unsigned int cnt = g_cnt[row];
    if (tid == 0) g_cnt[row] = 0u;    // reset for next graph replay
    int C;

    if (cnt >= (unsigned)TOPK && cnt <= (unsigned)CAP) {
        C = (int)cnt;
        const unsigned long long* gb = &g_buf[(size_t)row * CAP];
        for (int i = tid; i < C; i += K2NT) sh.u64[i] = gb[i];
        __syncthreads();
    } else {
        // -------- exact fallback: histogram select + re-collect (rare) --------
        for (int i = tid; i < NBINS; i += K2NT) sh.u32[i] = 0u;
        __syncthreads();
        for (int i = tid; i < NVEC; i += K2NT) {
            float4 v = rp4[i];
            atomicAdd(&sh.u32[fkey(v.x) >> 20], 1u);
            atomicAdd(&sh.u32[fkey(v.y) >> 20], 1u);
            atomicAdd(&sh.u32[fkey(v.z) >> 20], 1u);
            atomicAdd(&sh.u32[fkey(v.w) >> 20], 1u);
        }
        __syncthreads();
        if (tid < NCHUNK) {
            unsigned int s = 0;
            #pragma unroll 8
            for (int j = 0; j < 32; j++) s += sh.u32[tid * 32 + j];
            chunkSum[tid] = s;
        }
        __syncthreads();
        if (tid == 0) {
            unsigned int cum = 0; int b = 0;
            for (int c = NCHUNK - 1; c >= 0; c--) {
                if (cum + chunkSum[c] >= (unsigned)TOPK) {
                    for (int j = 31; j >= 0; j--) {
                        int bin = c * 32 + j; cum += sh.u32[bin];
                        if (cum >= (unsigned)TOPK) { b = bin; break; }
                    }
                    break;
                }
                cum += chunkSum[c];
            }
            s_cntAbove = cum - sh.u32[b];
            s_needRefine = (cum > (unsigned)CAP) ? 1 : 0;
            s_thr = ((unsigned int)b) << 20;
            s_cnt = 0u;
        }
        __syncthreads();
        if (s_needRefine) {
            const unsigned int bb = s_thr >> 20;
            const unsigned int above = s_cntAbove;
            for (int i = tid; i < NBINS; i += K2NT) sh.u32[i] = 0u;
            __syncthreads();
            for (int i = tid; i < NVEC; i += K2NT) {
                float4 v = rp4[i];
                unsigned int k0 = fkey(v.x), k1 = fkey(v.y), k2 = fkey(v.z), k3 = fkey(v.w);
                if ((k0 >> 20) == bb) atomicAdd(&sh.u32[(k0 >> 8) & 0xFFFu], 1u);
                if ((k1 >> 20) == bb) atomicAdd(&sh.u32[(k1 >> 8) & 0xFFFu], 1u);
                if ((k2 >> 20) == bb) atomicAdd(&sh.u32[(k2 >> 8) & 0xFFFu], 1u);
                if ((k3 >> 20) == bb) atomicAdd(&sh.u32[(k3 >> 8) & 0xFFFu], 1u);
            }
            __syncthreads();
            if (tid < NCHUNK) {
                unsigned int s = 0;
                #pragma unroll 8
                for (int j = 0; j < 32; j++) s += sh.u32[tid * 32 + j];
                chunkSum[tid] = s;
            }
            __syncthreads();
            if (tid == 0) {
                unsigned int cum = above; int b2 = 0;
                for (int c = NCHUNK - 1; c >= 0; c--) {
                    if (cum + chunkSum[c] >= (unsigned)TOPK) {
                        for (int j = 31; j >= 0; j--) {
                            int bin = c * 32 + j; cum += sh.u32[bin];
                            if (cum >= (unsigned)TOPK) { b2 = bin; break; }
                        }
                        break;
                    }
                    cum += chunkSum[c];
                }
                s_thr = (bb << 20) | (((unsigned int)b2) << 8);
                s_cnt = 0u;
            }
            __syncthreads();
        }
        {
            const unsigned int T = s_thr;
            const int refine = s_needRefine;
            for (int i = tid; i < NVEC; i += K2NT) {
                float4 v = rp4[i];
                unsigned int k[4] = {fkey(v.x), fkey(v.y), fkey(v.z), fkey(v.w)};
                unsigned int g = (unsigned int)(i * 4);
                #pragma unroll
                for (int c = 0; c < 4; c++) {
                    unsigned int kc = k[c];
                    bool pass = refine ? ((kc >> 8) >= (T >> 8)) : (kc >= T);
                    if (pass) {
                        unsigned p = atomicAdd(&s_cnt, 1u);
                        if (p < CAP) sh.u64[p] = ((unsigned long long)kc << 32) | (unsigned long long)(0xFFFFFFFFu - (g + (unsigned)c));
                    }
                }
            }
        }
        __syncthreads();
        C = (int)min(s_cnt, (unsigned)CAP);
    }

    // -------- bitonic sort (desc value, asc index) --------
    int N2 = 64; while (N2 < C) N2 <<= 1;
    for (int i = C + tid; i < N2; i += K2NT) sh.u64[i] = 0ULL;
    __syncthreads();
    for (unsigned int k = 2; k <= (unsigned)N2; k <<= 1) {
        for (unsigned int j = k >> 1; j > 0; j >>= 1) {
            for (unsigned int i = tid; i < (unsigned)N2; i += K2NT) {
                unsigned int ixj = i ^ j;
                if (ixj > i) {
                    unsigned long long a = sh.u64[i], c = sh.u64[ixj];
                    bool up = ((i & k) == 0u);
                    if (up ? (a < c) : (a > c)) { sh.u64[i] = c; sh.u64[ixj] = a; }
                }
            }
            __syncthreads();
        }
    }

    // -------- top-p over sorted top-50 --------
    if (tid == 0) {
        int kk = (C < TOPK) ? C : TOPK;
        float vmax = unkey((unsigned int)(sh.u64[0] >> 32));
        float e[TOPK];
        float s = 0.0f;
        for (int i = 0; i < kk; i++) {
            e[i] = expf(unkey((unsigned int)(sh.u64[i] >> 32)) - vmax);
            s += e[i];
        }
        float cum = 0.0f;
        int m = kk;
        for (int i = 0; i < kk; i++) {
            cum += e[i] / s;
            if (cum > TOPP) { m = i + 1; break; }
        }
        s_m = m;
    }
    __syncthreads();

    // -------- scatter kept values --------
    if (tid < s_m) {
        unsigned long long b = sh.u64[tid];
        unsigned int g = 0xFFFFFFFFu - (unsigned int)(b & 0xFFFFFFFFu);
        out[(size_t)row * VOCAB + g] = unkey((unsigned int)(b >> 32));
    }
}

extern "C" void kernel_launch(void* const* d_in, const int* in_sizes, int n_in,
                              void* d_out, int out_size) {
    const float* logits = (const float*)d_in[0];
    float* out = (float*)d_out;
    int rows = in_sizes[0] / VOCAB;          // 256
    dim3 g1(SEGS, rows);
    k1_stream<<<g1, K1NT>>>(logits, out);
    k2_finalize<<<rows, K2NT>>>(logits, out);
}

// round 12
// speedup vs baseline: 1.0120x; 1.0120x over previous
#include <cuda_runtime.h>
#include <math.h>

#define VOCAB   128000
#define NVEC    (VOCAB / 4)
#define TOPK    50
#define TOPP    0.9f
#define NEGV    (-1000000000.0f)
#define NBINS   4096
#define NCHUNK  (NBINS / 32)
#define CAP     2048
#define ROWSMAX 256
#define SEGS    25
#define VPSEG   (NVEC / SEGS)     // 1280 float4 per segment = 5 * 256
#define K1NT    256
#define K2NT    256
#define LCAP    192               // per-tile candidate staging
#define THRVAL  3.0f              // fixed candidate threshold (fallback covers misses)
#define POISON  (1u << 20)        // forces k2 exact fallback when a tile clips

__device__ unsigned int g_cnt[ROWSMAX];
__device__ unsigned long long g_buf[ROWSMAX * CAP];

__device__ __forceinline__ unsigned int fkey(float f) {
    unsigned int u = __float_as_uint(f);
    return (u & 0x80000000u) ? ~u : (u | 0x80000000u);
}
__device__ __forceinline__ float unkey(unsigned int k) {
    return __uint_as_float((k & 0x80000000u) ? (k & 0x7FFFFFFFu) : ~k);
}

// ---------------- K1: stream read + NEG-fill + tiny candidate collect ----------------
__global__ __launch_bounds__(K1NT)
void k1_stream(const float* __restrict__ logits, float* __restrict__ out) {
    __shared__ unsigned long long lbuf[LCAP];
    __shared__ unsigned int s_c;
    __shared__ unsigned int s_base;

    const int row = blockIdx.y;
    const int seg = blockIdx.x;
    const float4* rp4 = (const float4*)(logits + (size_t)row * VOCAB);
    float4* op4 = (float4*)(out + (size_t)row * VOCAB);
    const int tid = threadIdx.x;
    if (tid == 0) s_c = 0u;
    __syncthreads();

    const float4 neg4 = make_float4(NEGV, NEGV, NEGV, NEGV);
    const int i0 = seg * VPSEG + tid;

    // ---- 5-wide batch: streaming loads first, then write-through stores ----
    float4 v0 = __ldcs(&rp4[i0]);
    float4 v1 = __ldcs(&rp4[i0 + K1NT]);
    float4 v2 = __ldcs(&rp4[i0 + 2 * K1NT]);
    float4 v3 = __ldcs(&rp4[i0 + 3 * K1NT]);
    float4 v4 = __ldcs(&rp4[i0 + 4 * K1NT]);
    __stwt(&op4[i0],            neg4);
    __stwt(&op4[i0 + K1NT],     neg4);
    __stwt(&op4[i0 + 2 * K1NT], neg4);
    __stwt(&op4[i0 + 3 * K1NT], neg4);
    __stwt(&op4[i0 + 4 * K1NT], neg4);

    #define PROCESS(v, idx)                                                              \
    do {                                                                                 \
        float mx = fmaxf(fmaxf((v).x, (v).y), fmaxf((v).z, (v).w));                      \
        if (mx >= THRVAL) {                                                              \
            unsigned int g = (unsigned int)((idx) * 4);                                  \
            float vals[4] = {(v).x, (v).y, (v).z, (v).w};                                \
            _Pragma("unroll")                                                            \
            for (int c = 0; c < 4; c++) {                                                \
                if (vals[c] >= THRVAL) {                                                 \
                    unsigned p = atomicAdd(&s_c, 1u);                                    \
                    if (p < LCAP)                                                        \
                        lbuf[p] = ((unsigned long long)fkey(vals[c]) << 32)              \
                                | (unsigned long long)(0xFFFFFFFFu - (g + (unsigned)c)); \
                }                                                                        \
            }                                                                            \
        }                                                                                \
    } while (0)

    PROCESS(v0, i0);
    PROCESS(v1, i0 + K1NT);
    PROCESS(v2, i0 + 2 * K1NT);
    PROCESS(v3, i0 + 3 * K1NT);
    PROCESS(v4, i0 + 4 * K1NT);
    #undef PROCESS

    __syncthreads();

    const unsigned int cnt = s_c;
    if (cnt == 0u) return;
    const unsigned int stored = cnt < LCAP ? cnt : LCAP;
    if (tid == 0) {
        unsigned int add = (cnt > LCAP) ? (cnt + POISON) : cnt;  // clip -> force fallback
        s_base = atomicAdd(&g_cnt[row], add);
    }
    __syncthreads();
    const unsigned int b0 = s_base;
    unsigned long long* gb = &g_buf[(size_t)row * CAP];
    for (unsigned int i = tid; i < stored; i += K1NT) {
        unsigned int p = b0 + i;
        if (p < CAP) gb[p] = lbuf[i];
    }
}

// ---------------- K2: per-row finalize ----------------
__global__ __launch_bounds__(K2NT)
void k2_finalize(const float* __restrict__ logits, float* __restrict__ out) {
    __shared__ union {
        unsigned long long u64[CAP];
        unsigned int       u32[NBINS];
    } sh;
    __shared__ unsigned int chunkSum[NCHUNK];
    __shared__ unsigned int s_cnt;
    __shared__ unsigned int s_thr;
    __shared__ unsigned int s_cntAbove;
    __shared__ int s_needRefine;
    __shared__ int s_m;

    const int row = blockIdx.x;
    const float4* rp4 = (const float4*)(logits + (size_t)row * VOCAB);
    const int tid = threadIdx.x;

    const unsigned int cnt = g_cnt[row];
    if (tid == 0) g_cnt[row] = 0u;    // reset for next graph replay
    int C;

    if (cnt >= (unsigned)TOPK && cnt <= (unsigned)CAP) {
        C = (int)cnt;
        const unsigned long long* gb = &g_buf[(size_t)row * CAP];
        for (int i = tid; i < C; i += K2NT) sh.u64[i] = gb[i];
        __syncthreads();
    } else {
        // -------- exact fallback: histogram select + re-collect (rare) --------
        for (int i = tid; i < NBINS; i += K2NT) sh.u32[i] = 0u;
        __syncthreads();
        for (int i = tid; i < NVEC; i += K2NT) {
            float4 v = rp4[i];
            atomicAdd(&sh.u32[fkey(v.x) >> 20], 1u);
            atomicAdd(&sh.u32[fkey(v.y) >> 20], 1u);
            atomicAdd(&sh.u32[fkey(v.z) >> 20], 1u);
            atomicAdd(&sh.u32[fkey(v.w) >> 20], 1u);
        }
        __syncthreads();
        if (tid < NCHUNK) {
            unsigned int s = 0;
            #pragma unroll 8
            for (int j = 0; j < 32; j++) s += sh.u32[tid * 32 + j];
            chunkSum[tid] = s;
        }
        __syncthreads();
        if (tid == 0) {
            unsigned int cum = 0; int b = 0;
            for (int c = NCHUNK - 1; c >= 0; c--) {
                if (cum + chunkSum[c] >= (unsigned)TOPK) {
                    for (int j = 31; j >= 0; j--) {
                        int bin = c * 32 + j; cum += sh.u32[bin];
                        if (cum >= (unsigned)TOPK) { b = bin; break; }
                    }
                    break;
                }
                cum += chunkSum[c];
            }
            s_cntAbove = cum - sh.u32[b];
            s_needRefine = (cum > (unsigned)CAP) ? 1 : 0;
            s_thr = ((unsigned int)b) << 20;
            s_cnt = 0u;
        }
        __syncthreads();
        if (s_needRefine) {
            const unsigned int bb = s_thr >> 20;
            const unsigned int above = s_cntAbove;
            for (int i = tid; i < NBINS; i += K2NT) sh.u32[i] = 0u;
            __syncthreads();
            for (int i = tid; i < NVEC; i += K2NT) {
                float4 v = rp4[i];
                unsigned int k0 = fkey(v.x), k1 = fkey(v.y), k2 = fkey(v.z), k3 = fkey(v.w);
                if ((k0 >> 20) == bb) atomicAdd(&sh.u32[(k0 >> 8) & 0xFFFu], 1u);
                if ((k1 >> 20) == bb) atomicAdd(&sh.u32[(k1 >> 8) & 0xFFFu], 1u);
                if ((k2 >> 20) == bb) atomicAdd(&sh.u32[(k2 >> 8) & 0xFFFu], 1u);
                if ((k3 >> 20) == bb) atomicAdd(&sh.u32[(k3 >> 8) & 0xFFFu], 1u);
            }
            __syncthreads();
            if (tid < NCHUNK) {
                unsigned int s = 0;
                #pragma unroll 8
                for (int j = 0; j < 32; j++) s += sh.u32[tid * 32 + j];
                chunkSum[tid] = s;
            }
            __syncthreads();
            if (tid == 0) {
                unsigned int cum = above; int b2 = 0;
                for (int c = NCHUNK - 1; c >= 0; c--) {
                    if (cum + chunkSum[c] >= (unsigned)TOPK) {
                        for (int j = 31; j >= 0; j--) {
                            int bin = c * 32 + j; cum += sh.u32[bin];
                            if (cum >= (unsigned)TOPK) { b2 = bin; break; }
                        }
                        break;
                    }
                    cum += chunkSum[c];
                }
                s_thr = (bb << 20) | (((unsigned int)b2) << 8);
                s_cnt = 0u;
            }
            __syncthreads();
        }
        {
            const unsigned int T = s_thr;
            const int refine = s_needRefine;
            for (int i = tid; i < NVEC; i += K2NT) {
                float4 v = rp4[i];
                unsigned int k[4] = {fkey(v.x), fkey(v.y), fkey(v.z), fkey(v.w)};
                unsigned int g = (unsigned int)(i * 4);
                #pragma unroll
                for (int c = 0; c < 4; c++) {
                    unsigned int kc = k[c];
                    bool pass = refine ? ((kc >> 8) >= (T >> 8)) : (kc >= T);
                    if (pass) {
                        unsigned p = atomicAdd(&s_cnt, 1u);
                        if (p < CAP) sh.u64[p] = ((unsigned long long)kc << 32) | (unsigned long long)(0xFFFFFFFFu - (g + (unsigned)c));
                    }
                }
            }
        }
        __syncthreads();
        C = (int)min(s_cnt, (unsigned)CAP);
    }

    // -------- bitonic sort (desc value, asc index) --------
    int N2 = 64; while (N2 < C) N2 <<= 1;
    for (int i = C + tid; i < N2; i += K2NT) sh.u64[i] = 0ULL;
    __syncthreads();
    for (unsigned int k = 2; k <= (unsigned)N2; k <<= 1) {
        for (unsigned int j = k >> 1; j > 0; j >>= 1) {
            for (unsigned int i = tid; i < (unsigned)N2; i += K2NT) {
                unsigned int ixj = i ^ j;
                if (ixj > i) {
                    unsigned long long a = sh.u64[i], c = sh.u64[ixj];
                    bool up = ((i & k) == 0u);
                    if (up ? (a < c) : (a > c)) { sh.u64[i] = c; sh.u64[ixj] = a; }
                }
            }
            __syncthreads();
        }
    }

    // -------- top-p over sorted top-50 --------
    if (tid == 0) {
        int kk = (C < TOPK) ? C : TOPK;
        float vmax = unkey((unsigned int)(sh.u64[0] >> 32));
        float e[TOPK];
        float s = 0.0f;
        for (int i = 0; i < kk; i++) {
            e[i] = expf(unkey((unsigned int)(sh.u64[i] >> 32)) - vmax);
            s += e[i];
        }
        float cum = 0.0f;
        int m = kk;
        for (int i = 0; i < kk; i++) {
            cum += e[i] / s;
            if (cum > TOPP) { m = i + 1; break; }
        }
        s_m = m;
    }
    __syncthreads();

    // -------- scatter kept values --------
    if (tid < s_m) {
        unsigned long long b = sh.u64[tid];
        unsigned int g = 0xFFFFFFFFu - (unsigned int)(b & 0xFFFFFFFFu);
        out[(size_t)row * VOCAB + g] = unkey((unsigned int)(b >> 32));
    }
}

extern "C" void kernel_launch(void* const* d_in, const int* in_sizes, int n_in,
                              void* d_out, int out_size) {
    const float* logits = (const float*)d_in[0];
    float* out = (float*)d_out;
    int rows = in_sizes[0] / VOCAB;          // 256
    dim3 g1(SEGS, rows);
    k1_stream<<<g1, K1NT>>>(logits, out);
    k2_finalize<<<rows, K2NT>>>(logits, out);
}

// round 14
// speedup vs baseline: 1.0345x; 1.0223x over previous
#include <cuda_runtime.h>
#include <math.h>

#define VOCAB   128000
#define NVEC    (VOCAB / 4)
#define TOPK    50
#define TOPP    0.9f
#define NEGV    (-1000000000.0f)
#define NBINS   4096
#define NCHUNK  (NBINS / 32)
#define CAP     2048
#define ROWSMAX 256
#define SEGS    50
#define VPSEG   (NVEC / SEGS)     // 640 float4 per segment = 5 * 128
#define K1NT    128
#define K2NT    256
#define LCAP    128               // per-tile candidate staging
#define THRVAL  3.0f              // fixed candidate threshold (fallback covers misses)
#define POISON  (1u << 20)        // forces k2 exact fallback when a tile clips

__device__ unsigned int g_cnt[ROWSMAX];
__device__ unsigned long long g_buf[ROWSMAX * CAP];

__device__ __forceinline__ unsigned int fkey(float f) {
    unsigned int u = __float_as_uint(f);
    return (u & 0x80000000u) ? ~u : (u | 0x80000000u);
}
__device__ __forceinline__ float unkey(unsigned int k) {
    return __uint_as_float((k & 0x80000000u) ? (k & 0x7FFFFFFFu) : ~k);
}

// ---------------- K1: stream read + NEG-fill + tiny candidate collect ----------------
__global__ __launch_bounds__(K1NT)
void k1_stream(const float* __restrict__ logits, float* __restrict__ out) {
    __shared__ unsigned long long lbuf[LCAP];
    __shared__ unsigned int s_c;
    __shared__ unsigned int s_base;

    const int row = blockIdx.y;
    const int seg = blockIdx.x;
    const float4* rp4 = (const float4*)(logits + (size_t)row * VOCAB);
    float4* op4 = (float4*)(out + (size_t)row * VOCAB);
    const int tid = threadIdx.x;
    if (tid == 0) s_c = 0u;
    __syncthreads();

    const float4 neg4 = make_float4(NEGV, NEGV, NEGV, NEGV);
    const int i0 = seg * VPSEG + tid;

    // ---- 5-wide batch: all loads first, then all stores ----
    float4 v0 = rp4[i0];
    float4 v1 = rp4[i0 + K1NT];
    float4 v2 = rp4[i0 + 2 * K1NT];
    float4 v3 = rp4[i0 + 3 * K1NT];
    float4 v4 = rp4[i0 + 4 * K1NT];
    op4[i0]            = neg4;
    op4[i0 + K1NT]     = neg4;
    op4[i0 + 2 * K1NT] = neg4;
    op4[i0 + 3 * K1NT] = neg4;
    op4[i0 + 4 * K1NT] = neg4;

    #define PROCESS(v, idx)                                                              \
    do {                                                                                 \
        float mx = fmaxf(fmaxf((v).x, (v).y), fmaxf((v).z, (v).w));                      \
        if (mx >= THRVAL) {                                                              \
            unsigned int g = (unsigned int)((idx) * 4);                                  \
            float vals[4] = {(v).x, (v).y, (v).z, (v).w};                                \
            _Pragma("unroll")                                                            \
            for (int c = 0; c < 4; c++) {                                                \
                if (vals[c] >= THRVAL) {                                                 \
                    unsigned p = atomicAdd(&s_c, 1u);                                    \
                    if (p < LCAP)                                                        \
                        lbuf[p] = ((unsigned long long)fkey(vals[c]) << 32)              \
                                | (unsigned long long)(0xFFFFFFFFu - (g + (unsigned)c)); \
                }                                                                        \
            }                                                                            \
        }                                                                                \
    } while (0)

    PROCESS(v0, i0);
    PROCESS(v1, i0 + K1NT);
    PROCESS(v2, i0 + 2 * K1NT);
    PROCESS(v3, i0 + 3 * K1NT);
    PROCESS(v4, i0 + 4 * K1NT);
    #undef PROCESS

    __syncthreads();

    const unsigned int cnt = s_c;
    if (cnt == 0u) return;
    const unsigned int stored = cnt < LCAP ? cnt : LCAP;
    if (tid == 0) {
        unsigned int add = (cnt > LCAP) ? (cnt + POISON) : cnt;  // clip -> force fallback
        s_base = atomicAdd(&g_cnt[row], add);
    }
    __syncthreads();
    const unsigned int b0 = s_base;
    unsigned long long* gb = &g_buf[(size_t)row * CAP];
    for (unsigned int i = tid; i < stored; i += K1NT) {
        unsigned int p = b0 + i;
        if (p < CAP) gb[p] = lbuf[i];
    }
}

// ---------------- K2: per-row finalize ----------------
__global__ __launch_bounds__(K2NT)
void k2_finalize(const float* __restrict__ logits, float* __restrict__ out) {
    __shared__ union {
        unsigned long long u64[CAP];
        unsigned int       u32[NBINS];
    } sh;
    __shared__ unsigned long long sorted[TOPK];
    __shared__ unsigned int chunkSum[NCHUNK];
    __shared__ unsigned int s_total;
    __shared__ unsigned int s_cnt;
    __shared__ unsigned int s_thr;
    __shared__ unsigned int s_cntAbove;
    __shared__ int s_needRefine;
    __shared__ int s_m;

    const int row = blockIdx.x;
    const float4* rp4 = (const float4*)(logits + (size_t)row * VOCAB);
    const int tid = threadIdx.x;

    // RACE FIX: single reader-resetter publishes the count via smem; everyone
    // reads the published copy AFTER the barrier. (The old pattern let late
    // warps read the already-reset 0 -> divergent __syncthreads -> UB.)
    if (tid == 0) {
        s_total = g_cnt[row];
        g_cnt[row] = 0u;      // reset for next graph replay
    }
    __syncthreads();
    const unsigned int cnt = s_total;
    int C;

    if (cnt >= (unsigned)TOPK && cnt <= (unsigned)CAP) {
        C = (int)cnt;
        const unsigned long long* gb = &g_buf[(size_t)row * CAP];
        for (int i = tid; i < C; i += K2NT) sh.u64[i] = gb[i];
        __syncthreads();
    } else {
        // -------- exact fallback: histogram select + re-collect (rare) --------
        for (int i = tid; i < NBINS; i += K2NT) sh.u32[i] = 0u;
        __syncthreads();
        for (int i = tid; i < NVEC; i += K2NT) {
            float4 v = rp4[i];
            atomicAdd(&sh.u32[fkey(v.x) >> 20], 1u);
            atomicAdd(&sh.u32[fkey(v.y) >> 20], 1u);
            atomicAdd(&sh.u32[fkey(v.z) >> 20], 1u);
            atomicAdd(&sh.u32[fkey(v.w) >> 20], 1u);
        }
        __syncthreads();
        if (tid < NCHUNK) {
            unsigned int s = 0;
            #pragma unroll 8
            for (int j = 0; j < 32; j++) s += sh.u32[tid * 32 + j];
            chunkSum[tid] = s;
        }
        __syncthreads();
        if (tid == 0) {
            unsigned int cum = 0; int b = 0;
            for (int c = NCHUNK - 1; c >= 0; c--) {
                if (cum + chunkSum[c] >= (unsigned)TOPK) {
                    for (int j = 31; j >= 0; j--) {
                        int bin = c * 32 + j; cum += sh.u32[bin];
                        if (cum >= (unsigned)TOPK) { b = bin; break; }
                    }
                    break;
                }
                cum += chunkSum[c];
            }
            s_cntAbove = cum - sh.u32[b];
            s_needRefine = (cum > (unsigned)CAP) ? 1 : 0;
            s_thr = ((unsigned int)b) << 20;
            s_cnt = 0u;
        }
        __syncthreads();
        if (s_needRefine) {
            const unsigned int bb = s_thr >> 20;
            const unsigned int above = s_cntAbove;
            for (int i = tid; i < NBINS; i += K2NT) sh.u32[i] = 0u;
            __syncthreads();
            for (int i = tid; i < NVEC; i += K2NT) {
                float4 v = rp4[i];
                unsigned int k0 = fkey(v.x), k1 = fkey(v.y), k2 = fkey(v.z), k3 = fkey(v.w);
                if ((k0 >> 20) == bb) atomicAdd(&sh.u32[(k0 >> 8) & 0xFFFu], 1u);
                if ((k1 >> 20) == bb) atomicAdd(&sh.u32[(k1 >> 8) & 0xFFFu], 1u);
                if ((k2 >> 20) == bb) atomicAdd(&sh.u32[(k2 >> 8) & 0xFFFu], 1u);
                if ((k3 >> 20) == bb) atomicAdd(&sh.u32[(k3 >> 8) & 0xFFFu], 1u);
            }
            __syncthreads();
            if (tid < NCHUNK) {
                unsigned int s = 0;
                #pragma unroll 8
                for (int j = 0; j < 32; j++) s += sh.u32[tid * 32 + j];
                chunkSum[tid] = s;
            }
            __syncthreads();
            if (tid == 0) {
                unsigned int cum = above; int b2 = 0;
                for (int c = NCHUNK - 1; c >= 0; c--) {
                    if (cum + chunkSum[c] >= (unsigned)TOPK) {
                        for (int j = 31; j >= 0; j--) {
                            int bin = c * 32 + j; cum += sh.u32[bin];
                            if (cum >= (unsigned)TOPK) { b2 = bin; break; }
                        }
                        break;
                    }
                    cum += chunkSum[c];
                }
                s_thr = (bb << 20) | (((unsigned int)b2) << 8);
                s_cnt = 0u;
            }
            __syncthreads();
        }
        {
            const unsigned int T = s_thr;
            const int refine = s_needRefine;
            for (int i = tid; i < NVEC; i += K2NT) {
                float4 v = rp4[i];
                unsigned int k[4] = {fkey(v.x), fkey(v.y), fkey(v.z), fkey(v.w)};
                unsigned int g = (unsigned int)(i * 4);
                #pragma unroll
                for (int c = 0; c < 4; c++) {
                    unsigned int kc = k[c];
                    bool pass = refine ? ((kc >> 8) >= (T >> 8)) : (kc >= T);
                    if (pass) {
                        unsigned p = atomicAdd(&s_cnt, 1u);
                        if (p < CAP) sh.u64[p] = ((unsigned long long)kc << 32) | (unsigned long long)(0xFFFFFFFFu - (g + (unsigned)c));
                    }
                }
            }
        }
        __syncthreads();
        C = (int)min(s_cnt, (unsigned)CAP);
    }

    // -------- rank selection: keys are unique, only ranks < TOPK matter --------
    for (int i = tid; i < C; i += K2NT) {
        unsigned long long e = sh.u64[i];
        int r = 0;
        int j = 0;
        for (; j + 4 <= C; j += 4) {
            r += (sh.u64[j]     > e);
            r += (sh.u64[j + 1] > e);
            r += (sh.u64[j + 2] > e);
            r += (sh.u64[j + 3] > e);
        }
        for (; j < C; j++) r += (sh.u64[j] > e);
        if (r < TOPK) sorted[r] = e;
    }
    __syncthreads();

    // -------- top-p over sorted top-50 --------
    if (tid == 0) {
        int kk = (C < TOPK) ? C : TOPK;
        float vmax = unkey((unsigned int)(sorted[0] >> 32));
        float e[TOPK];
        float s = 0.0f;
        for (int i = 0; i < kk; i++) {
            e[i] = expf(unkey((unsigned int)(sorted[i] >> 32)) - vmax);
            s += e[i];
        }
        float cum = 0.0f;
        int m = kk;
        for (int i = 0; i < kk; i++) {
            cum += e[i] / s;
            if (cum > TOPP) { m = i + 1; break; }
        }
        s_m = m;
    }
    __syncthreads();

    // -------- scatter kept values --------
    if (tid < s_m) {
        unsigned long long b = sorted[tid];
        unsigned int g = 0xFFFFFFFFu - (unsigned int)(b & 0xFFFFFFFFu);
        out[(size_t)row * VOCAB + g] = unkey((unsigned int)(b >> 32));
    }
}

extern "C" void kernel_launch(void* const* d_in, const int* in_sizes, int n_in,
                              void* d_out, int out_size) {
    const float* logits = (const float*)d_in[0];
    float* out = (float*)d_out;
    int rows = in_sizes[0] / VOCAB;          // 256
    dim3 g1(SEGS, rows);
    k1_stream<<<g1, K1NT>>>(logits, out);
    k2_finalize<<<rows, K2NT>>>(logits, out);
}

// round 15
// speedup vs baseline: 1.0351x; 1.0006x over previous
#include <cuda_runtime.h>
#include <math.h>

#define VOCAB   128000
#define NVEC    (VOCAB / 4)
#define TOPK    50
#define TOPP    0.9f
#define NEGV    (-1000000000.0f)
#define NBINS   4096
#define NCHUNK  (NBINS / 32)
#define CAP     2048
#define ROWSMAX 256
#define SEGS    50
#define VPSEG   (NVEC / SEGS)     // 640 float4 per segment = 5 * 128
#define K1NT    128
#define K2NT    256
#define LCAP    128               // per-tile candidate staging
#define THRVAL  3.0f              // fixed candidate threshold (fallback covers misses)
#define POISON  (1u << 20)        // forces k2 exact fallback when a tile clips

__device__ unsigned int g_cnt[ROWSMAX];
__device__ unsigned long long g_buf[ROWSMAX * CAP];

__device__ __forceinline__ unsigned int fkey(float f) {
    unsigned int u = __float_as_uint(f);
    return (u & 0x80000000u) ? ~u : (u | 0x80000000u);
}
__device__ __forceinline__ float unkey(unsigned int k) {
    return __uint_as_float((k & 0x80000000u) ? (k & 0x7FFFFFFFu) : ~k);
}

// ---------------- K1: stream read + NEG-fill + tiny candidate collect ----------------
__global__ __launch_bounds__(K1NT)
void k1_stream(const float* __restrict__ logits, float* __restrict__ out) {
    __shared__ unsigned long long lbuf[LCAP];
    __shared__ unsigned int s_c;
    __shared__ unsigned int s_base;

    const int row = blockIdx.y;
    const int seg = blockIdx.x;
    const float4* rp4 = (const float4*)(logits + (size_t)row * VOCAB);
    float4* op4 = (float4*)(out + (size_t)row * VOCAB);
    const int tid = threadIdx.x;
    if (tid == 0) s_c = 0u;
    __syncthreads();

    const float4 neg4 = make_float4(NEGV, NEGV, NEGV, NEGV);
    const int i0 = seg * VPSEG + tid;

    // ---- 5-wide batch: all loads first, then all stores ----
    float4 v0 = rp4[i0];
    float4 v1 = rp4[i0 + K1NT];
    float4 v2 = rp4[i0 + 2 * K1NT];
    float4 v3 = rp4[i0 + 3 * K1NT];
    float4 v4 = rp4[i0 + 4 * K1NT];
    op4[i0]            = neg4;
    op4[i0 + K1NT]     = neg4;
    op4[i0 + 2 * K1NT] = neg4;
    op4[i0 + 3 * K1NT] = neg4;
    op4[i0 + 4 * K1NT] = neg4;

    #define PROCESS(v, idx)                                                              \
    do {                                                                                 \
        float mx = fmaxf(fmaxf((v).x, (v).y), fmaxf((v).z, (v).w));                      \
        if (mx >= THRVAL) {                                                              \
            unsigned int g = (unsigned int)((idx) * 4);                                  \
            float vals[4] = {(v).x, (v).y, (v).z, (v).w};                                \
            _Pragma("unroll")                                                            \
            for (int c = 0; c < 4; c++) {                                                \
                if (vals[c] >= THRVAL) {                                                 \
                    unsigned p = atomicAdd(&s_c, 1u);                                    \
                    if (p < LCAP)                                                        \
                        lbuf[p] = ((unsigned long long)fkey(vals[c]) << 32)              \
                                | (unsigned long long)(0xFFFFFFFFu - (g + (unsigned)c)); \
                }                                                                        \
            }                                                                            \
        }                                                                                \
    } while (0)

    PROCESS(v0, i0);
    PROCESS(v1, i0 + K1NT);
    PROCESS(v2, i0 + 2 * K1NT);
    PROCESS(v3, i0 + 3 * K1NT);
    PROCESS(v4, i0 + 4 * K1NT);
    #undef PROCESS

    __syncthreads();

    const unsigned int cnt = s_c;
    if (cnt == 0u) return;
    const unsigned int stored = cnt < LCAP ? cnt : LCAP;
    if (tid == 0) {
        unsigned int add = (cnt > LCAP) ? (cnt + POISON) : cnt;  // clip -> force fallback
        s_base = atomicAdd(&g_cnt[row], add);
    }
    __syncthreads();
    const unsigned int b0 = s_base;
    unsigned long long* gb = &g_buf[(size_t)row * CAP];
    for (unsigned int i = tid; i < stored; i += K1NT) {
        unsigned int p = b0 + i;
        if (p < CAP) gb[p] = lbuf[i];
    }
}

// ---------------- K2: per-row finalize ----------------
__global__ __launch_bounds__(K2NT)
void k2_finalize(const float* __restrict__ logits, float* __restrict__ out) {
    __shared__ union {
        unsigned long long u64[CAP];
        unsigned int       u32[NBINS];
    } sh;
    __shared__ unsigned long long sorted[TOPK];
    __shared__ float s_e[TOPK];
    __shared__ unsigned int chunkSum[NCHUNK];
    __shared__ unsigned int s_total;
    __shared__ unsigned int s_cnt;
    __shared__ unsigned int s_thr;
    __shared__ unsigned int s_cntAbove;
    __shared__ int s_needRefine;
    __shared__ int s_m;

    const int row = blockIdx.x;
    const float4* rp4 = (const float4*)(logits + (size_t)row * VOCAB);
    const int tid = threadIdx.x;

    // Race-safe count read+reset: single thread publishes via smem.
    if (tid == 0) {
        s_total = g_cnt[row];
        g_cnt[row] = 0u;      // reset for next graph replay
    }
    __syncthreads();
    const unsigned int cnt = s_total;
    int C;

    if (cnt >= (unsigned)TOPK && cnt <= (unsigned)CAP) {
        C = (int)cnt;
        const unsigned long long* gb = &g_buf[(size_t)row * CAP];
        for (int i = tid; i < C; i += K2NT) sh.u64[i] = gb[i];
        __syncthreads();
    } else {
        // -------- exact fallback: histogram select + re-collect (rare) --------
        for (int i = tid; i < NBINS; i += K2NT) sh.u32[i] = 0u;
        __syncthreads();
        for (int i = tid; i < NVEC; i += K2NT) {
            float4 v = rp4[i];
            atomicAdd(&sh.u32[fkey(v.x) >> 20], 1u);
            atomicAdd(&sh.u32[fkey(v.y) >> 20], 1u);
            atomicAdd(&sh.u32[fkey(v.z) >> 20], 1u);
            atomicAdd(&sh.u32[fkey(v.w) >> 20], 1u);
        }
        __syncthreads();
        if (tid < NCHUNK) {
            unsigned int s = 0;
            #pragma unroll 8
            for (int j = 0; j < 32; j++) s += sh.u32[tid * 32 + j];
            chunkSum[tid] = s;
        }
        __syncthreads();
        if (tid == 0) {
            unsigned int cum = 0; int b = 0;
            for (int c = NCHUNK - 1; c >= 0; c--) {
                if (cum + chunkSum[c] >= (unsigned)TOPK) {
                    for (int j = 31; j >= 0; j--) {
                        int bin = c * 32 + j; cum += sh.u32[bin];
                        if (cum >= (unsigned)TOPK) { b = bin; break; }
                    }
                    break;
                }
                cum += chunkSum[c];
            }
            s_cntAbove = cum - sh.u32[b];
            s_needRefine = (cum > (unsigned)CAP) ? 1 : 0;
            s_thr = ((unsigned int)b) << 20;
            s_cnt = 0u;
        }
        __syncthreads();
        if (s_needRefine) {
            const unsigned int bb = s_thr >> 20;
            const unsigned int above = s_cntAbove;
            for (int i = tid; i < NBINS; i += K2NT) sh.u32[i] = 0u;
            __syncthreads();
            for (int i = tid; i < NVEC; i += K2NT) {
                float4 v = rp4[i];
                unsigned int k0 = fkey(v.x), k1 = fkey(v.y), k2 = fkey(v.z), k3 = fkey(v.w);
                if ((k0 >> 20) == bb) atomicAdd(&sh.u32[(k0 >> 8) & 0xFFFu], 1u);
                if ((k1 >> 20) == bb) atomicAdd(&sh.u32[(k1 >> 8) & 0xFFFu], 1u);
                if ((k2 >> 20) == bb) atomicAdd(&sh.u32[(k2 >> 8) & 0xFFFu], 1u);
                if ((k3 >> 20) == bb) atomicAdd(&sh.u32[(k3 >> 8) & 0xFFFu], 1u);
            }
            __syncthreads();
            if (tid < NCHUNK) {
                unsigned int s = 0;
                #pragma unroll 8
                for (int j = 0; j < 32; j++) s += sh.u32[tid * 32 + j];
                chunkSum[tid] = s;
            }
            __syncthreads();
            if (tid == 0) {
                unsigned int cum = above; int b2 = 0;
                for (int c = NCHUNK - 1; c >= 0; c--) {
                    if (cum + chunkSum[c] >= (unsigned)TOPK) {
                        for (int j = 31; j >= 0; j--) {
                            int bin = c * 32 + j; cum += sh.u32[bin];
                            if (cum >= (unsigned)TOPK) { b2 = bin; break; }
                        }
                        break;
                    }
                    cum += chunkSum[c];
                }
                s_thr = (bb << 20) | (((unsigned int)b2) << 8);
                s_cnt = 0u;
            }
            __syncthreads();
        }
        {
            const unsigned int T = s_thr;
            const int refine = s_needRefine;
            for (int i = tid; i < NVEC; i += K2NT) {
                float4 v = rp4[i];
                unsigned int k[4] = {fkey(v.x), fkey(v.y), fkey(v.z), fkey(v.w)};
                unsigned int g = (unsigned int)(i * 4);
                #pragma unroll
                for (int c = 0; c < 4; c++) {
                    unsigned int kc = k[c];
                    bool pass = refine ? ((kc >> 8) >= (T >> 8)) : (kc >= T);
                    if (pass) {
                        unsigned p = atomicAdd(&s_cnt, 1u);
                        if (p < CAP) sh.u64[p] = ((unsigned long long)kc << 32) | (unsigned long long)(0xFFFFFFFFu - (g + (unsigned)c));
                    }
                }
            }
        }
        __syncthreads();
        C = (int)min(s_cnt, (unsigned)CAP);
    }

    // -------- rank selection: keys are unique, only ranks < TOPK matter --------
    for (int i = tid; i < C; i += K2NT) {
        unsigned long long e = sh.u64[i];
        int r = 0;
        int j = 0;
        for (; j + 4 <= C; j += 4) {
            r += (sh.u64[j]     > e);
            r += (sh.u64[j + 1] > e);
            r += (sh.u64[j + 2] > e);
            r += (sh.u64[j + 3] > e);
        }
        for (; j < C; j++) r += (sh.u64[j] > e);
        if (r < TOPK) sorted[r] = e;
    }
    __syncthreads();

    // -------- top-p over sorted top-50: exps in parallel, cheap serial scan --------
    const int kk = (C < TOPK) ? C : TOPK;
    {
        float vmax = unkey((unsigned int)(sorted[0] >> 32));
        if (tid < kk)
            s_e[tid] = expf(unkey((unsigned int)(sorted[tid] >> 32)) - vmax);
    }
    __syncthreads();
    if (tid == 0) {
        float s = 0.0f;
        for (int i = 0; i < kk; i++) s += s_e[i];   // same order as before
        float cum = 0.0f;
        int m = kk;
        for (int i = 0; i < kk; i++) {
            cum += s_e[i] / s;                       // same op order as reference path
            if (cum > TOPP) { m = i + 1; break; }
        }
        s_m = m;
    }
    __syncthreads();

    // -------- scatter kept values --------
    if (tid < s_m) {
        unsigned long long b = sorted[tid];
        unsigned int g = 0xFFFFFFFFu - (unsigned int)(b & 0xFFFFFFFFu);
        out[(size_t)row * VOCAB + g] = unkey((unsigned int)(b >> 32));
    }
}

extern "C" void kernel_launch(void* const* d_in, const int* in_sizes, int n_in,
                              void* d_out, int out_size) {
    const float* logits = (const float*)d_in[0];
    float* out = (float*)d_out;
    int rows = in_sizes[0] / VOCAB;          // 256
    dim3 g1(SEGS, rows);
    k1_stream<<<g1, K1NT>>>(logits, out);
    k2_finalize<<<rows, K2NT>>>(logits, out);
}

// round 16
// speedup vs baseline: 1.0654x; 1.0293x over previous
#include <cuda_runtime.h>
#include <math.h>

#define VOCAB   128000
#define NVEC    (VOCAB / 4)
#define TOPK    50
#define TOPP    0.9f
#define NEGV    (-1000000000.0f)
#define NBINS   4096
#define NCHUNK  (NBINS / 32)
#define CAP     2048
#define ROWSMAX 256
#define SEGS    50
#define VPSEG   (NVEC / SEGS)     // 640 float4 per segment = 5 * 128
#define K1NT    128
#define K2NT    256
#define LCAP    128               // per-tile candidate staging
#define THRVAL  3.0f              // fixed candidate threshold (fallback covers misses)
#define POISON  (1u << 20)        // forces k2 exact fallback when a tile clips

__device__ unsigned int g_cnt[ROWSMAX];
__device__ unsigned long long g_buf[ROWSMAX * CAP];

__device__ __forceinline__ unsigned int fkey(float f) {
    unsigned int u = __float_as_uint(f);
    return (u & 0x80000000u) ? ~u : (u | 0x80000000u);
}
__device__ __forceinline__ float unkey(unsigned int k) {
    return __uint_as_float((k & 0x80000000u) ? (k & 0x7FFFFFFFu) : ~k);
}

// ---------------- K1: stream read + NEG-fill + tiny candidate collect ----------------
__global__ __launch_bounds__(K1NT)
void k1_stream(const float* __restrict__ logits, float* __restrict__ out) {
    __shared__ unsigned long long lbuf[LCAP];
    __shared__ unsigned int s_c;
    __shared__ unsigned int s_base;

    const int row = blockIdx.y;
    const int seg = blockIdx.x;
    const float4* rp4 = (const float4*)(logits + (size_t)row * VOCAB);
    float4* op4 = (float4*)(out + (size_t)row * VOCAB);
    const int tid = threadIdx.x;
    if (tid == 0) s_c = 0u;
    __syncthreads();

    const float4 neg4 = make_float4(NEGV, NEGV, NEGV, NEGV);
    const int i0 = seg * VPSEG + tid;

    // ---- 5-wide batch: all loads first, then all stores ----
    float4 v0 = rp4[i0];
    float4 v1 = rp4[i0 + K1NT];
    float4 v2 = rp4[i0 + 2 * K1NT];
    float4 v3 = rp4[i0 + 3 * K1NT];
    float4 v4 = rp4[i0 + 4 * K1NT];
    op4[i0]            = neg4;
    op4[i0 + K1NT]     = neg4;
    op4[i0 + 2 * K1NT] = neg4;
    op4[i0 + 3 * K1NT] = neg4;
    op4[i0 + 4 * K1NT] = neg4;

    #define PROCESS(v, idx)                                                              \
    do {                                                                                 \
        float mx = fmaxf(fmaxf((v).x, (v).y), fmaxf((v).z, (v).w));                      \
        if (mx >= THRVAL) {                                                              \
            unsigned int g = (unsigned int)((idx) * 4);                                  \
            float vals[4] = {(v).x, (v).y, (v).z, (v).w};                                \
            _Pragma("unroll")                                                            \
            for (int c = 0; c < 4; c++) {                                                \
                if (vals[c] >= THRVAL) {                                                 \
                    unsigned p = atomicAdd(&s_c, 1u);                                    \
                    if (p < LCAP)                                                        \
                        lbuf[p] = ((unsigned long long)fkey(vals[c]) << 32)              \
                                | (unsigned long long)(0xFFFFFFFFu - (g + (unsigned)c)); \
                }                                                                        \
            }                                                                            \
        }                                                                                \
    } while (0)

    PROCESS(v0, i0);
    PROCESS(v1, i0 + K1NT);
    PROCESS(v2, i0 + 2 * K1NT);
    PROCESS(v3, i0 + 3 * K1NT);
    PROCESS(v4, i0 + 4 * K1NT);
    #undef PROCESS

    __syncthreads();

    const unsigned int cnt = s_c;
    if (cnt == 0u) return;
    const unsigned int stored = cnt < LCAP ? cnt : LCAP;
    if (tid == 0) {
        unsigned int add = (cnt > LCAP) ? (cnt + POISON) : cnt;  // clip -> force fallback
        s_base = atomicAdd(&g_cnt[row], add);
    }
    __syncthreads();
    const unsigned int b0 = s_base;
    unsigned long long* gb = &g_buf[(size_t)row * CAP];
    for (unsigned int i = tid; i < stored; i += K1NT) {
        unsigned int p = b0 + i;
        if (p < CAP) gb[p] = lbuf[i];
    }
}

// ---------------- K2: per-row finalize ----------------
__global__ __launch_bounds__(K2NT)
void k2_finalize(const float* __restrict__ logits, float* __restrict__ out) {
    __shared__ union {
        unsigned long long u64[CAP];
        unsigned int       u32[NBINS];
    } sh;
    __shared__ unsigned long long sorted[TOPK];
    __shared__ float s_e[TOPK];
    __shared__ unsigned int chunkSum[NCHUNK];
    __shared__ unsigned int s_total;
    __shared__ unsigned int s_cnt;
    __shared__ unsigned int s_thr;
    __shared__ unsigned int s_cntAbove;
    __shared__ int s_needRefine;
    __shared__ int s_m;

    const int row = blockIdx.x;
    const float4* rp4 = (const float4*)(logits + (size_t)row * VOCAB);
    const int tid = threadIdx.x;

    // Speculative candidate prefetch (overlaps with the count round-trip).
    const unsigned long long* gb = &g_buf[(size_t)row * CAP];
    const unsigned long long pre = gb[tid];   // always-valid memory (CAP >= K2NT)

    // Race-safe count read+reset: single thread publishes via smem.
    if (tid == 0) {
        s_total = g_cnt[row];
        g_cnt[row] = 0u;      // reset for next graph replay
    }
    __syncthreads();
    const unsigned int cnt = s_total;
    int C;

    if (cnt >= (unsigned)TOPK && cnt <= (unsigned)CAP) {
        C = (int)cnt;
        if (C <= K2NT) {
            sh.u64[tid] = pre;                     // prefetched path (typical: C ~ 173)
        } else {
            for (int i = tid; i < C; i += K2NT) sh.u64[i] = gb[i];
        }
        __syncthreads();
    } else {
        // -------- exact fallback: histogram select + re-collect (rare) --------
        for (int i = tid; i < NBINS; i += K2NT) sh.u32[i] = 0u;
        __syncthreads();
        for (int i = tid; i < NVEC; i += K2NT) {
            float4 v = rp4[i];
            atomicAdd(&sh.u32[fkey(v.x) >> 20], 1u);
            atomicAdd(&sh.u32[fkey(v.y) >> 20], 1u);
            atomicAdd(&sh.u32[fkey(v.z) >> 20], 1u);
            atomicAdd(&sh.u32[fkey(v.w) >> 20], 1u);
        }
        __syncthreads();
        if (tid < NCHUNK) {
            unsigned int s = 0;
            #pragma unroll 8
            for (int j = 0; j < 32; j++) s += sh.u32[tid * 32 + j];
            chunkSum[tid] = s;
        }
        __syncthreads();
        if (tid == 0) {
            unsigned int cum = 0; int b = 0;
            for (int c = NCHUNK - 1; c >= 0; c--) {
                if (cum + chunkSum[c] >= (unsigned)TOPK) {
                    for (int j = 31; j >= 0; j--) {
                        int bin = c * 32 + j; cum += sh.u32[bin];
                        if (cum >= (unsigned)TOPK) { b = bin; break; }
                    }
                    break;
                }
                cum += chunkSum[c];
            }
            s_cntAbove = cum - sh.u32[b];
            s_needRefine = (cum > (unsigned)CAP) ? 1 : 0;
            s_thr = ((unsigned int)b) << 20;
            s_cnt = 0u;
        }
        __syncthreads();
        if (s_needRefine) {
            const unsigned int bb = s_thr >> 20;
            const unsigned int above = s_cntAbove;
            for (int i = tid; i < NBINS; i += K2NT) sh.u32[i] = 0u;
            __syncthreads();
            for (int i = tid; i < NVEC; i += K2NT) {
                float4 v = rp4[i];
                unsigned int k0 = fkey(v.x), k1 = fkey(v.y), k2 = fkey(v.z), k3 = fkey(v.w);
                if ((k0 >> 20) == bb) atomicAdd(&sh.u32[(k0 >> 8) & 0xFFFu], 1u);
                if ((k1 >> 20) == bb) atomicAdd(&sh.u32[(k1 >> 8) & 0xFFFu], 1u);
                if ((k2 >> 20) == bb) atomicAdd(&sh.u32[(k2 >> 8) & 0xFFFu], 1u);
                if ((k3 >> 20) == bb) atomicAdd(&sh.u32[(k3 >> 8) & 0xFFFu], 1u);
            }
            __syncthreads();
            if (tid < NCHUNK) {
                unsigned int s = 0;
                #pragma unroll 8
                for (int j = 0; j < 32; j++) s += sh.u32[tid * 32 + j];
                chunkSum[tid] = s;
            }
            __syncthreads();
            if (tid == 0) {
                unsigned int cum = above; int b2 = 0;
                for (int c = NCHUNK - 1; c >= 0; c--) {
                    if (cum + chunkSum[c] >= (unsigned)TOPK) {
                        for (int j = 31; j >= 0; j--) {
                            int bin = c * 32 + j; cum += sh.u32[bin];
                            if (cum >= (unsigned)TOPK) { b2 = bin; break; }
                        }
                        break;
                    }
                    cum += chunkSum[c];
                }
                s_thr = (bb << 20) | (((unsigned int)b2) << 8);
                s_cnt = 0u;
            }
            __syncthreads();
        }
        {
            const unsigned int T = s_thr;
            const int refine = s_needRefine;
            for (int i = tid; i < NVEC; i += K2NT) {
                float4 v = rp4[i];
                unsigned int k[4] = {fkey(v.x), fkey(v.y), fkey(v.z), fkey(v.w)};
                unsigned int g = (unsigned int)(i * 4);
                #pragma unroll
                for (int c = 0; c < 4; c++) {
                    unsigned int kc = k[c];
                    bool pass = refine ? ((kc >> 8) >= (T >> 8)) : (kc >= T);
                    if (pass) {
                        unsigned p = atomicAdd(&s_cnt, 1u);
                        if (p < CAP) sh.u64[p] = ((unsigned long long)kc << 32) | (unsigned long long)(0xFFFFFFFFu - (g + (unsigned)c));
                    }
                }
            }
        }
        __syncthreads();
        C = (int)min(s_cnt, (unsigned)CAP);
    }

    // -------- rank selection: keys are unique, only ranks < TOPK matter --------
    for (int i = tid; i < C; i += K2NT) {
        unsigned long long e = sh.u64[i];
        int r = 0;
        int j = 0;
        for (; j + 4 <= C; j += 4) {
            r += (sh.u64[j]     > e);
            r += (sh.u64[j + 1] > e);
            r += (sh.u64[j + 2] > e);
            r += (sh.u64[j + 3] > e);
        }
        for (; j < C; j++) r += (sh.u64[j] > e);
        if (r < TOPK) sorted[r] = e;
    }
    __syncthreads();

    // -------- top-p over sorted top-50: fully parallel, bit-identical folds --------
    const int kk = (C < TOPK) ? C : TOPK;
    {
        float vmax = unkey((unsigned int)(sorted[0] >> 32));
        if (tid < kk)
            s_e[tid] = expf(unkey((unsigned int)(sorted[tid] >> 32)) - vmax);
        if (tid == 0) s_m = kk;     // default: no crossing keeps all kk
    }
    __syncthreads();
    if (tid < kk) {
        // Each thread replays the SAME fold-left sum (identical rounding to the
        // serial reference), then its own fold-left prefix of divided terms —
        // which is bit-identical to the serial loop's cum at index tid.
        float s = 0.0f;
        for (int j = 0; j < kk; j++) s += s_e[j];
        float cum = 0.0f;
        for (int j = 0; j <= tid; j++) cum += s_e[j] / s;
        if (cum > TOPP) atomicMin(&s_m, tid + 1);   // monotone cum -> min = first crossing
    }
    __syncthreads();

    // -------- scatter kept values --------
    if (tid < s_m) {
        unsigned long long b = sorted[tid];
        unsigned int g = 0xFFFFFFFFu - (unsigned int)(b & 0xFFFFFFFFu);
        out[(size_t)row * VOCAB + g] = unkey((unsigned int)(b >> 32));
    }
}

extern "C" void kernel_launch(void* const* d_in, const int* in_sizes, int n_in,
                              void* d_out, int out_size) {
    const float* logits = (const float*)d_in[0];
    float* out = (float*)d_out;
    int rows = in_sizes[0] / VOCAB;          // 256
    dim3 g1(SEGS, rows);
    k1_stream<<<g1, K1NT>>>(logits, out);
    k2_finalize<<<rows, K2NT>>>(logits, out);
}